// round 2
// baseline (speedup 1.0000x reference)
#include <cuda_runtime.h>

#define GW      1024
#define GH      1024
#define W_OUT   4096
#define H_OUT   4096
#define NCH     4
#define GPLANE  (GH * GW)          // 1048576
#define OPLANE  (H_OUT * W_OUT)    // 16777216

// Per-axis sampling tables (built once per launch by setup_kernel).
__device__ int   g_x0[W_OUT];
__device__ float g_wx[W_OUT];
__device__ int   g_y0[H_OUT];
__device__ float g_wy[H_OUT];

__device__ __forceinline__ void axis_entry(int v, int* p0, float* pw) {
    // Faithful fp32 replication of the reference chain:
    //   f = (v - 511.5)/511.5 ;  t = ((f + 1) * 0.5) * 1023 ; clip ; floor
    float fv = __fadd_rn((float)v, -511.5f);
    float f  = __fdiv_rn(fv, 511.5f);
    float t  = __fmul_rn(__fmul_rn(__fadd_rn(f, 1.0f), 0.5f), 1023.0f);
    t = fminf(fmaxf(t, 0.0f), 1023.0f);
    float f0 = floorf(t);
    *p0 = (int)f0;
    *pw = __fadd_rn(t, -f0);
}

__global__ void setup_kernel(const int* __restrict__ cs) {
    int i = blockIdx.x * blockDim.x + threadIdx.x;
    if (i >= W_OUT) return;
    int vx = (cs[0] + i) & (GW - 1);
    int vy = (cs[1] + i) & (GH - 1);
    axis_entry(vx, &g_x0[i], &g_wx[i]);
    axis_entry(vy, &g_y0[i], &g_wy[i]);
}

__global__ void __launch_bounds__(256) sample_kernel(const float* __restrict__ grid,
                                                     float* __restrict__ out) {
    int idx = blockIdx.x * blockDim.x + threadIdx.x;
    int x = idx & (W_OUT - 1);
    int y = idx >> 12;

    int   x0 = g_x0[x];
    float wx = g_wx[x];
    int   y0 = g_y0[y];   // warp-uniform
    float wy = g_wy[y];   // warp-uniform

    int x1 = min(x0 + 1, GW - 1);
    int y1 = min(y0 + 1, GH - 1);
    float omx = 1.0f - wx;
    float omy = 1.0f - wy;

    const float* r0 = grid + y0 * GW;
    const float* r1 = grid + y1 * GW;
    int obase = y * W_OUT + x;

#pragma unroll
    for (int c = 0; c < NCH; ++c) {
        const float* p0 = r0 + c * GPLANE;
        const float* p1 = r1 + c * GPLANE;
        float v00 = __ldg(p0 + x0);
        float v01 = __ldg(p0 + x1);
        float v10 = __ldg(p1 + x0);
        float v11 = __ldg(p1 + x1);
        float top = v00 * omx + v01 * wx;
        float bot = v10 * omx + v11 * wx;
        out[c * OPLANE + obase] = top * omy + bot * wy;
    }
}

extern "C" void kernel_launch(void* const* d_in, const int* in_sizes, int n_in,
                              void* d_out, int out_size) {
    const float* grid = (const float*)d_in[0];
    const int*   cs   = (const int*)d_in[1];
    float*       out  = (float*)d_out;

    setup_kernel<<<(W_OUT + 255) / 256, 256>>>(cs);
    sample_kernel<<<OPLANE / 256, 256>>>(grid, out);
}

// round 3
// speedup vs baseline: 1.8105x; 1.8105x over previous
#include <cuda_runtime.h>

#define GW      1024
#define GH      1024
#define W_OUT   4096
#define H_OUT   4096
#define NCH     4
#define GPLANE  (GH * GW)          // 1048576
#define OPLANE  (H_OUT * W_OUT)    // 16777216
#define TILE    1024               // period of the output in both axes

// Per-axis sampling tables — only TILE entries needed (output is periodic).
__device__ int   g_x0[TILE];
__device__ float g_wx[TILE];
__device__ int   g_y0[TILE];
__device__ float g_wy[TILE];

__device__ __forceinline__ void axis_entry(int v, int* p0, float* pw) {
    // Faithful fp32 replication of the reference chain:
    //   f = (v - 511.5)/511.5 ;  t = ((f + 1) * 0.5) * 1023 ; clip ; floor
    float fv = __fadd_rn((float)v, -511.5f);
    float f  = __fdiv_rn(fv, 511.5f);
    float t  = __fmul_rn(__fmul_rn(__fadd_rn(f, 1.0f), 0.5f), 1023.0f);
    t = fminf(fmaxf(t, 0.0f), 1023.0f);
    float f0 = floorf(t);
    *p0 = (int)f0;
    *pw = __fadd_rn(t, -f0);
}

__global__ void setup_kernel(const int* __restrict__ cs) {
    int i = blockIdx.x * blockDim.x + threadIdx.x;
    if (i >= TILE) return;
    int vx = (cs[0] + i) & (GW - 1);
    int vy = (cs[1] + i) & (GH - 1);
    axis_entry(vx, &g_x0[i], &g_wx[i]);
    axis_entry(vy, &g_y0[i], &g_wy[i]);
}

// One thread per UNIQUE pixel (1024x1024). Computes the 4 channel values once,
// then broadcasts each to its 16 periodic replicas in the 4096x4096 output.
__global__ void __launch_bounds__(256) sample_rep_kernel(const float* __restrict__ grid,
                                                         float* __restrict__ out) {
    int t = blockIdx.x * blockDim.x + threadIdx.x;   // 0 .. 1048575
    int x = t & (TILE - 1);
    int y = t >> 10;

    int   x0 = g_x0[x];
    float wx = g_wx[x];
    int   y0 = g_y0[y];   // warp-uniform
    float wy = g_wy[y];   // warp-uniform

    int x1 = min(x0 + 1, GW - 1);
    int y1 = min(y0 + 1, GH - 1);
    float omx = 1.0f - wx;
    float omy = 1.0f - wy;

    const float* r0 = grid + y0 * GW;
    const float* r1 = grid + y1 * GW;

    float v[NCH];
#pragma unroll
    for (int c = 0; c < NCH; ++c) {
        const float* p0 = r0 + c * GPLANE;
        const float* p1 = r1 + c * GPLANE;
        float v00 = __ldg(p0 + x0);
        float v01 = __ldg(p0 + x1);
        float v10 = __ldg(p1 + x0);
        float v11 = __ldg(p1 + x1);
        float top = v00 * omx + v01 * wx;
        float bot = v10 * omx + v11 * wx;
        v[c] = top * omy + bot * wy;
    }

    // Replicate: 16 positions per channel. All stores fully coalesced
    // (lanes cover consecutive x). Offsets are compile-time constants.
    int obase = y * W_OUT + x;
#pragma unroll
    for (int c = 0; c < NCH; ++c) {
        float* po = out + c * OPLANE + obase;
        float val = v[c];
#pragma unroll
        for (int dy = 0; dy < 4; ++dy) {
#pragma unroll
            for (int dx = 0; dx < 4; ++dx) {
                po[dy * (TILE * W_OUT) + dx * TILE] = val;
            }
        }
    }
}

extern "C" void kernel_launch(void* const* d_in, const int* in_sizes, int n_in,
                              void* d_out, int out_size) {
    const float* grid = (const float*)d_in[0];
    const int*   cs   = (const int*)d_in[1];
    float*       out  = (float*)d_out;

    setup_kernel<<<(TILE + 255) / 256, 256>>>(cs);
    sample_rep_kernel<<<(TILE * TILE) / 256, 256>>>(grid, out);
}

// round 5
// speedup vs baseline: 1.9400x; 1.0716x over previous
#include <cuda_runtime.h>

#define GW      1024
#define GH      1024
#define W_OUT   4096
#define H_OUT   4096
#define NCH     4
#define GPLANE  (GH * GW)          // 1048576
#define OPLANE  (H_OUT * W_OUT)    // 16777216
#define TILE    1024               // period of the output in both axes

// Faithful fp32 replication of the reference coordinate chain:
//   f = (v - 511.5)/511.5 ; t = ((f + 1) * 0.5) * 1023 ; clip ; floor
__device__ __forceinline__ void axis_entry(int v, int* p0, float* pw) {
    float fv = __fadd_rn((float)v, -511.5f);
    float f  = __fdiv_rn(fv, 511.5f);
    float t  = __fmul_rn(__fmul_rn(__fadd_rn(f, 1.0f), 0.5f), 1023.0f);
    t = fminf(fmaxf(t, 0.0f), 1023.0f);
    float f0 = floorf(t);
    *p0 = (int)f0;
    *pw = __fadd_rn(t, -f0);
}

// Single fused kernel. 1024 blocks = 1024 unique rows; 256 threads/block,
// 4 consecutive-x pixels per thread (one float4 store quantum).
// Each pixel-quad is replicated to 16 periodic positions per channel.
__global__ void __launch_bounds__(256) sample_rep4_kernel(const float* __restrict__ grid,
                                                          const int* __restrict__ cs,
                                                          float* __restrict__ out) {
    const int y     = blockIdx.x;              // 0..1023 (unique tile row)
    const int xbase = threadIdx.x * 4;         // 0..1020

    const int cs0 = cs[0];                     // L2-broadcast
    const int cs1 = cs[1];

    // y-axis entry (block-uniform)
    int y0; float wy;
    axis_entry((cs1 + y) & (GH - 1), &y0, &wy);
    const int   y1  = min(y0 + 1, GH - 1);
    const float omy = 1.0f - wy;

    // x-axis entries for the 4 pixels
    int   x0[4], x1[4];
    float wx[4], omx[4];
#pragma unroll
    for (int i = 0; i < 4; ++i) {
        axis_entry((cs0 + xbase + i) & (GW - 1), &x0[i], &wx[i]);
        x1[i]  = min(x0[i] + 1, GW - 1);
        omx[i] = 1.0f - wx[i];
    }

    const float* r0 = grid + y0 * GW;
    const float* r1 = grid + y1 * GW;

    // Compute 4 channels x 4 pixels
    float4 v[NCH];
#pragma unroll
    for (int c = 0; c < NCH; ++c) {
        const float* p0 = r0 + c * GPLANE;
        const float* p1 = r1 + c * GPLANE;
        float q[4];
#pragma unroll
        for (int i = 0; i < 4; ++i) {
            float v00 = __ldg(p0 + x0[i]);
            float v01 = __ldg(p0 + x1[i]);
            float v10 = __ldg(p1 + x0[i]);
            float v11 = __ldg(p1 + x1[i]);
            float top = v00 * omx[i] + v01 * wx[i];
            float bot = v10 * omx[i] + v11 * wx[i];
            q[i] = top * omy + bot * wy;
        }
        v[c] = make_float4(q[0], q[1], q[2], q[3]);
    }

    // Replicate to 16 periodic positions per channel with streaming float4 stores.
    const int obase = y * W_OUT + xbase;       // float index; 16B-aligned
#pragma unroll
    for (int c = 0; c < NCH; ++c) {
        float4* po = (float4*)(out + c * OPLANE + obase);
        const float4 val = v[c];
#pragma unroll
        for (int dy = 0; dy < 4; ++dy) {
#pragma unroll
            for (int dx = 0; dx < 4; ++dx) {
                __stcs(po + (dy * (TILE * W_OUT) + dx * TILE) / 4, val);
            }
        }
    }
}

extern "C" void kernel_launch(void* const* d_in, const int* in_sizes, int n_in,
                              void* d_out, int out_size) {
    const float* grid = (const float*)d_in[0];
    const int*   cs   = (const int*)d_in[1];
    float*       out  = (float*)d_out;

    sample_rep4_kernel<<<TILE, 256>>>(grid, cs, out);
}